// round 12
// baseline (speedup 1.0000x reference)
#include <cuda_runtime.h>

#define BATCH 65536
#define IN1   784
#define HD    128
#define KOUTD 64
#define NGRID 10
#define NOUTD 10

// Scratch for hidden activations h = x@w1^T + b1  (65536 x 128 fp32 = 33.5 MB)
__device__ float g_h[(size_t)BATCH * HD];

// ---------------- packed f32x2 helpers ----------------
__device__ __forceinline__ unsigned long long dpack(float x, float y) {
    unsigned long long d;
    asm("mov.b64 %0, {%1, %2};" : "=l"(d) : "f"(x), "f"(y));
    return d;
}
__device__ __forceinline__ void dunpack(unsigned long long d, float &x, float &y) {
    asm("mov.b64 {%0, %1}, %2;" : "=f"(x), "=f"(y) : "l"(d));
}
__device__ __forceinline__ void ffma2(unsigned long long &c, unsigned long long a,
                                      unsigned long long b) {
    asm("fma.rn.f32x2 %0, %1, %2, %0;" : "+l"(c) : "l"(a), "l"(b));
}

// =====================================================================
// Kernel A: h = x @ w1^T + b1    (65536x784) @ (784x128) -> (65536x128)
// Block tile 128(M) x 128(N), K chunks of 16, double-buffered smem,
// 256 threads, 8x8 microtile, accumulators packed f32x2 over M-pairs.
// =====================================================================
#define KC   16
#define ASTR 132   // padded row stride (floats), multiple of 4 for 16B loads

__global__ void __launch_bounds__(256, 2) k_gemm1(
    const float* __restrict__ x, const float* __restrict__ w1,
    const float* __restrict__ b1)
{
    __shared__ __align__(16) float As[2][KC][ASTR];
    __shared__ __align__(16) float Bs[2][KC][ASTR];

    const int tid = threadIdx.x;
    const int tn  = tid & 15;        // 16 n-groups of 8 cols
    const int tm  = tid >> 4;        // 16 m-groups of 8 rows
    const long b0 = (long)blockIdx.x * 128;
    const float* xp = x + b0 * IN1;

    unsigned long long acc[4][8];    // [m-pair][n] packed (row 2i, row 2i+1)
    #pragma unroll
    for (int i = 0; i < 4; i++)
        #pragma unroll
        for (int j = 0; j < 8; j++) acc[i][j] = 0ull;

    float4 ra[2], rb[2];

    auto loadg = [&](int k0) {
        #pragma unroll
        for (int i = 0; i < 2; i++) {
            int id  = tid + 256 * i;
            int row = id >> 2;       // 0..127
            int kq  = id & 3;        // 0..3 (float4 quarter of the 16-wide chunk)
            ra[i] = *(const float4*)(xp + (long)row * IN1 + k0 + kq * 4);
            rb[i] = *(const float4*)(w1 + (long)row * IN1 + k0 + kq * 4);
        }
    };
    auto stores = [&](int buf) {
        #pragma unroll
        for (int i = 0; i < 2; i++) {
            int id  = tid + 256 * i;
            int row = id >> 2;
            int kq  = id & 3;
            const float* pa = (const float*)&ra[i];
            const float* pb = (const float*)&rb[i];
            #pragma unroll
            for (int j = 0; j < 4; j++) {
                As[buf][kq * 4 + j][row] = pa[j];
                Bs[buf][kq * 4 + j][row] = pb[j];
            }
        }
    };

    loadg(0);
    stores(0);
    __syncthreads();

    const int NIT = IN1 / KC;        // 49
    for (int t = 0; t < NIT; t++) {
        int buf = t & 1;
        if (t + 1 < NIT) loadg((t + 1) * KC);

        #pragma unroll
        for (int kk = 0; kk < KC; kk++) {
            ulonglong2 a0 = *(const ulonglong2*)&As[buf][kk][tm * 8];
            ulonglong2 a1 = *(const ulonglong2*)&As[buf][kk][tm * 8 + 4];
            float4 v0 = *(const float4*)&Bs[buf][kk][tn * 8];
            float4 v1 = *(const float4*)&Bs[buf][kk][tn * 8 + 4];
            unsigned long long ad[4] = {a0.x, a0.y, a1.x, a1.y};
            float bf[8] = {v0.x, v0.y, v0.z, v0.w, v1.x, v1.y, v1.z, v1.w};
            #pragma unroll
            for (int j = 0; j < 8; j++) {
                unsigned long long bd = dpack(bf[j], bf[j]);
                #pragma unroll
                for (int i2 = 0; i2 < 4; i2++) ffma2(acc[i2][j], ad[i2], bd);
            }
        }

        if (t + 1 < NIT) {
            stores((t + 1) & 1);
            __syncthreads();
        }
    }

    // epilogue: + b1, write h
    float bias[8];
    *(float4*)&bias[0] = *(const float4*)&b1[tn * 8];
    *(float4*)&bias[4] = *(const float4*)&b1[tn * 8 + 4];

    float rr[8][8];
    #pragma unroll
    for (int i2 = 0; i2 < 4; i2++)
        #pragma unroll
        for (int j = 0; j < 8; j++)
            dunpack(acc[i2][j], rr[2 * i2][j], rr[2 * i2 + 1][j]);

    #pragma unroll
    for (int r = 0; r < 8; r++) {
        long row = b0 + tm * 8 + r;
        float4 o0 = make_float4(rr[r][0] + bias[0], rr[r][1] + bias[1],
                                rr[r][2] + bias[2], rr[r][3] + bias[3]);
        float4 o1 = make_float4(rr[r][4] + bias[4], rr[r][5] + bias[5],
                                rr[r][6] + bias[6], rr[r][7] + bias[7]);
        *(float4*)&g_h[row * HD + tn * 8]     = o0;
        *(float4*)&g_h[row * HD + tn * 8 + 4] = o1;
    }
}

// =====================================================================
// Kernel B: psi = ricker(h * k), y = einsum(psi, coef) + wbias,
//           out = y @ w2^T + b2
// Block = 128 batch rows. i-chunks of 4 (L-chunk = 40). 256 threads.
// GEMM microtile: 4 b-rows (2 packed pairs) x 8 o-cols per thread.
// =====================================================================
#define IC    4
#define LCH   (IC * NGRID)   // 40
#define NCHNK (HD / IC)      // 32
#define PSTR  132
#define CSTR  72
#define YSTR  66
#define RICKER_C 0.8673250705840776f

__global__ void __launch_bounds__(256) k_kan(
    const float* __restrict__ coef, const float* __restrict__ wbias,
    const float* __restrict__ w2, const float* __restrict__ b2,
    float* __restrict__ out)
{
    __shared__ __align__(16) union {
        struct { float Ps[LCH][PSTR]; float Cs[LCH][CSTR]; } s;
        float Ys[128][YSTR];
    } sm;
    __shared__ float W2s[NOUTD][65];
    __shared__ float b2s[NOUTD];

    const int tid = threadIdx.x;
    const long b0 = (long)blockIdx.x * 128;
    const int og  = tid & 7;     // 8 o-groups of 8
    const int bg  = tid >> 3;    // 32 b-groups of 4

    if (tid < NOUTD) b2s[tid] = b2[tid];
    for (int i = tid; i < NOUTD * KOUTD; i += 256) W2s[i / 64][i % 64] = w2[i];

    // init accumulators with wbias (both packed halves share the same o)
    unsigned long long acc[2][8];
    {
        float wb[8];
        *(float4*)&wb[0] = *(const float4*)&wbias[og * 8];
        *(float4*)&wb[4] = *(const float4*)&wbias[og * 8 + 4];
        #pragma unroll
        for (int j = 0; j < 8; j++) {
            unsigned long long v = dpack(wb[j], wb[j]);
            acc[0][j] = v;
            acc[1][j] = v;
        }
    }

    for (int ic = 0; ic < NCHNK; ic++) {
        __syncthreads();   // previous chunk's GEMM readers are done

        // ---- psi into Ps[l][b], l = il*10 + (g-1) ----
        #pragma unroll
        for (int q = 0; q < 2; q++) {
            int id = q * 256 + tid;          // 0..511 = 128 b x 4 il
            int il = id & 3;
            int b  = id >> 2;
            float hv = g_h[(b0 + b) * HD + ic * IC + il];
            #pragma unroll
            for (int g = 1; g <= NGRID; g++) {
                float t  = hv * (float)g;
                float t2 = t * t;
                float e  = __expf(-0.5f * t2);
                sm.s.Ps[il * NGRID + (g - 1)][b] = RICKER_C * (1.0f - t2) * e;
            }
        }
        // ---- coef chunk: Cs[l][o] = coef[o*1280 + ic*40 + l] ----
        #pragma unroll
        for (int f = 0; f < 10; f++) {
            int idx = f * 256 + tid;         // 0..2559
            int l = idx % LCH;
            int o = idx / LCH;
            sm.s.Cs[l][o] = coef[(long)o * (HD * NGRID) + ic * LCH + l];
        }
        __syncthreads();

        // ---- GEMM: acc[b-pair][o] += Ps[l][b] * Cs[l][o] ----
        #pragma unroll 8
        for (int l = 0; l < LCH; l++) {
            ulonglong2 pv = *(const ulonglong2*)&sm.s.Ps[l][bg * 4];
            float4 c0 = *(const float4*)&sm.s.Cs[l][og * 8];
            float4 c1 = *(const float4*)&sm.s.Cs[l][og * 8 + 4];
            float cf[8] = {c0.x, c0.y, c0.z, c0.w, c1.x, c1.y, c1.z, c1.w};
            #pragma unroll
            for (int j = 0; j < 8; j++) {
                unsigned long long bd = dpack(cf[j], cf[j]);
                ffma2(acc[0][j], pv.x, bd);
                ffma2(acc[1][j], pv.y, bd);
            }
        }
    }

    // ---- stage y through smem (aliases Ps/Cs — sync first) ----
    __syncthreads();
    #pragma unroll
    for (int i2 = 0; i2 < 2; i2++)
        #pragma unroll
        for (int j = 0; j < 8; j++) {
            float lo, hi;
            dunpack(acc[i2][j], lo, hi);
            sm.Ys[bg * 4 + 2 * i2][og * 8 + j]     = lo;
            sm.Ys[bg * 4 + 2 * i2 + 1][og * 8 + j] = hi;
        }
    __syncthreads();

    // ---- out[b][j] = sum_o y[b][o] * w2[j][o] + b2[j] ----
    #pragma unroll
    for (int r = 0; r < 5; r++) {
        int id = r * 256 + tid;              // 0..1279 = 128 b x 10 j
        int b  = id / NOUTD;
        int j  = id % NOUTD;
        float a = b2s[j];
        #pragma unroll 8
        for (int o = 0; o < KOUTD; o++) a += sm.Ys[b][o] * W2s[j][o];
        out[(b0 + b) * NOUTD + j] = a;
    }
}

// =====================================================================
extern "C" void kernel_launch(void* const* d_in, const int* in_sizes, int n_in,
                              void* d_out, int out_size)
{
    const float* x     = (const float*)d_in[0];
    const float* w1    = (const float*)d_in[1];
    const float* b1    = (const float*)d_in[2];
    const float* coef  = (const float*)d_in[3];
    const float* wbias = (const float*)d_in[4];
    const float* w2    = (const float*)d_in[5];
    const float* b2    = (const float*)d_in[6];
    float* out = (float*)d_out;

    k_gemm1<<<BATCH / 128, 256>>>(x, w1, b1);
    k_kan<<<BATCH / 128, 256>>>(coef, wbias, w2, b2, out);
}

// round 13
// speedup vs baseline: 1.0436x; 1.0436x over previous
#include <cuda_runtime.h>

#define BATCH 65536
#define IN1   784
#define HD    128
#define KOUTD 64
#define NGRID 10
#define NOUTD 10

// Scratch for hidden activations h = x@w1^T + b1  (65536 x 128 fp32 = 33.5 MB)
__device__ float g_h[(size_t)BATCH * HD];

// ---------------- packed f32x2 helpers ----------------
__device__ __forceinline__ unsigned long long dpack(float x, float y) {
    unsigned long long d;
    asm("mov.b64 %0, {%1, %2};" : "=l"(d) : "f"(x), "f"(y));
    return d;
}
__device__ __forceinline__ void dunpack(unsigned long long d, float &x, float &y) {
    asm("mov.b64 {%0, %1}, %2;" : "=f"(x), "=f"(y) : "l"(d));
}
__device__ __forceinline__ void ffma2(unsigned long long &c, unsigned long long a,
                                      unsigned long long b) {
    asm("fma.rn.f32x2 %0, %1, %2, %0;" : "+l"(c) : "l"(a), "l"(b));
}

// =====================================================================
// Kernel A: h = x @ w1^T + b1    (65536x784) @ (784x128) -> (65536x128)
// (unchanged from R12 — 128x128 tile, double-buffered, f32x2 accum)
// =====================================================================
#define KC   16
#define ASTR 132

__global__ void __launch_bounds__(256, 2) k_gemm1(
    const float* __restrict__ x, const float* __restrict__ w1,
    const float* __restrict__ b1)
{
    __shared__ __align__(16) float As[2][KC][ASTR];
    __shared__ __align__(16) float Bs[2][KC][ASTR];

    const int tid = threadIdx.x;
    const int tn  = tid & 15;
    const int tm  = tid >> 4;
    const long b0 = (long)blockIdx.x * 128;
    const float* xp = x + b0 * IN1;

    unsigned long long acc[4][8];
    #pragma unroll
    for (int i = 0; i < 4; i++)
        #pragma unroll
        for (int j = 0; j < 8; j++) acc[i][j] = 0ull;

    float4 ra[2], rb[2];

    auto loadg = [&](int k0) {
        #pragma unroll
        for (int i = 0; i < 2; i++) {
            int id  = tid + 256 * i;
            int row = id >> 2;
            int kq  = id & 3;
            ra[i] = *(const float4*)(xp + (long)row * IN1 + k0 + kq * 4);
            rb[i] = *(const float4*)(w1 + (long)row * IN1 + k0 + kq * 4);
        }
    };
    auto stores = [&](int buf) {
        #pragma unroll
        for (int i = 0; i < 2; i++) {
            int id  = tid + 256 * i;
            int row = id >> 2;
            int kq  = id & 3;
            const float* pa = (const float*)&ra[i];
            const float* pb = (const float*)&rb[i];
            #pragma unroll
            for (int j = 0; j < 4; j++) {
                As[buf][kq * 4 + j][row] = pa[j];
                Bs[buf][kq * 4 + j][row] = pb[j];
            }
        }
    };

    loadg(0);
    stores(0);
    __syncthreads();

    const int NIT = IN1 / KC;   // 49
    for (int t = 0; t < NIT; t++) {
        int buf = t & 1;
        if (t + 1 < NIT) loadg((t + 1) * KC);

        #pragma unroll
        for (int kk = 0; kk < KC; kk++) {
            ulonglong2 a0 = *(const ulonglong2*)&As[buf][kk][tm * 8];
            ulonglong2 a1 = *(const ulonglong2*)&As[buf][kk][tm * 8 + 4];
            float4 v0 = *(const float4*)&Bs[buf][kk][tn * 8];
            float4 v1 = *(const float4*)&Bs[buf][kk][tn * 8 + 4];
            unsigned long long ad[4] = {a0.x, a0.y, a1.x, a1.y};
            float bf[8] = {v0.x, v0.y, v0.z, v0.w, v1.x, v1.y, v1.z, v1.w};
            #pragma unroll
            for (int j = 0; j < 8; j++) {
                unsigned long long bd = dpack(bf[j], bf[j]);
                #pragma unroll
                for (int i2 = 0; i2 < 4; i2++) ffma2(acc[i2][j], ad[i2], bd);
            }
        }

        if (t + 1 < NIT) {
            stores((t + 1) & 1);
            __syncthreads();
        }
    }

    float bias[8];
    *(float4*)&bias[0] = *(const float4*)&b1[tn * 8];
    *(float4*)&bias[4] = *(const float4*)&b1[tn * 8 + 4];

    float rr[8][8];
    #pragma unroll
    for (int i2 = 0; i2 < 4; i2++)
        #pragma unroll
        for (int j = 0; j < 8; j++)
            dunpack(acc[i2][j], rr[2 * i2][j], rr[2 * i2 + 1][j]);

    #pragma unroll
    for (int r = 0; r < 8; r++) {
        long row = b0 + tm * 8 + r;
        float4 o0 = make_float4(rr[r][0] + bias[0], rr[r][1] + bias[1],
                                rr[r][2] + bias[2], rr[r][3] + bias[3]);
        float4 o1 = make_float4(rr[r][4] + bias[4], rr[r][5] + bias[5],
                                rr[r][6] + bias[6], rr[r][7] + bias[7]);
        *(float4*)&g_h[row * HD + tn * 8]     = o0;
        *(float4*)&g_h[row * HD + tn * 8 + 4] = o1;
    }
}

// =====================================================================
// Kernel B (rewritten): psi -> einsum -> w2.
// Block = 128 batch rows, 128 threads. i-chunks of 4 (L-chunk = 40).
// Microtile 8(b) x 8(o) per thread: 32 FFMA2 per l, 2 LDS.128 + 8 LDS.64.
// coef stored DUPLICATED in smem so the packed (c,c) f32x2 operand is a
// single LDS.64 (no MOV packing). Stride-18 og layout -> conflict-free.
// Epilogue: per-row 64->10 partial + butterfly shuffle over the 8 og lanes.
// =====================================================================
#define IC    4
#define LCH   (IC * NGRID)   // 40
#define NCHNK (HD / IC)      // 32
#define PSTR  136            // 128 + 8 pad
#define CSTR  144            // 8 og-groups * 18
#define RICKER_C 0.8673250705840776f

__global__ void __launch_bounds__(128, 4) k_kan(
    const float* __restrict__ coef, const float* __restrict__ wbias,
    const float* __restrict__ w2, const float* __restrict__ b2,
    float* __restrict__ out)
{
    __shared__ __align__(16) float Ps[LCH][PSTR];    // psi, l-major   (21.8 KB)
    __shared__ __align__(16) float Csd[LCH][CSTR];   // coef duplicated (23.0 KB)
    __shared__ float W2s[NOUTD][65];
    __shared__ float b2s[NOUTD];

    const int tid = threadIdx.x;
    const long b0 = (long)blockIdx.x * 128;
    const int og  = tid & 7;     // 8 o-groups of 8
    const int bg  = tid >> 3;    // 16 b-groups of 8 rows

    if (tid < NOUTD) b2s[tid] = b2[tid];
    #pragma unroll
    for (int i = tid; i < NOUTD * KOUTD; i += 128) W2s[i / 64][i % 64] = w2[i];

    // accumulators [b-pair 0..3][o 0..7], init with wbias (same o in both halves)
    unsigned long long acc[4][8];
    {
        float wb[8];
        *(float4*)&wb[0] = *(const float4*)&wbias[og * 8];
        *(float4*)&wb[4] = *(const float4*)&wbias[og * 8 + 4];
        #pragma unroll
        for (int j = 0; j < 8; j++) {
            unsigned long long v = dpack(wb[j], wb[j]);
            #pragma unroll
            for (int i = 0; i < 4; i++) acc[i][j] = v;
        }
    }

    for (int ic = 0; ic < NCHNK; ic++) {
        __syncthreads();   // previous chunk's readers done before overwrite

        // ---- psi: thread owns batch row b = tid; 4 il x 10 g values ----
        {
            float4 hv4 = *(const float4*)&g_h[(b0 + tid) * HD + ic * IC];
            float hv[4] = {hv4.x, hv4.y, hv4.z, hv4.w};
            #pragma unroll
            for (int il = 0; il < IC; il++) {
                #pragma unroll
                for (int g = 1; g <= NGRID; g++) {
                    float t  = hv[il] * (float)g;
                    float t2 = t * t;
                    float e  = __expf(-0.5f * t2);
                    Ps[il * NGRID + (g - 1)][tid] = RICKER_C * (1.0f - t2) * e;
                }
            }
        }
        // ---- coef chunk, duplicated: Csd[l][(o>>3)*18 + 2*(o&7)] = {c,c} ----
        #pragma unroll
        for (int f = 0; f < 20; f++) {
            int idx = f * 128 + tid;         // 0..2559 = 64 o x 40 l
            int o = idx / LCH;
            int l = idx % LCH;
            float c = coef[(long)o * (HD * NGRID) + ic * LCH + l];
            *(float2*)&Csd[l][(o >> 3) * 18 + 2 * (o & 7)] = make_float2(c, c);
        }
        __syncthreads();

        // ---- GEMM: acc[bp][o] += psi[l][b] * coef_dup[l][o] ----
        #pragma unroll 4
        for (int l = 0; l < LCH; l++) {
            ulonglong2 p0 = *(const ulonglong2*)&Ps[l][bg * 8];
            ulonglong2 p1 = *(const ulonglong2*)&Ps[l][bg * 8 + 4];
            unsigned long long pa[4] = {p0.x, p0.y, p1.x, p1.y};
            #pragma unroll
            for (int j = 0; j < 8; j++) {
                unsigned long long cd =
                    *(const unsigned long long*)&Csd[l][og * 18 + 2 * j];
                ffma2(acc[0][j], pa[0], cd);
                ffma2(acc[1][j], pa[1], cd);
                ffma2(acc[2][j], pa[2], cd);
                ffma2(acc[3][j], pa[3], cd);
            }
        }
    }

    // ---- epilogue: y @ w2^T + b2 via per-row partials + butterfly ----
    #pragma unroll
    for (int i = 0; i < 4; i++) {
        float ylo[8], yhi[8];
        #pragma unroll
        for (int j = 0; j < 8; j++) dunpack(acc[i][j], ylo[j], yhi[j]);
        #pragma unroll
        for (int hh = 0; hh < 2; hh++) {
            const float* yv = hh ? yhi : ylo;
            float pj[NOUTD];
            #pragma unroll
            for (int j10 = 0; j10 < NOUTD; j10++) {
                float s = 0.0f;
                #pragma unroll
                for (int oo = 0; oo < 8; oo++)
                    s += yv[oo] * W2s[j10][og * 8 + oo];
                pj[j10] = s;
            }
            #pragma unroll
            for (int m = 1; m <= 4; m <<= 1)
                #pragma unroll
                for (int j10 = 0; j10 < NOUTD; j10++)
                    pj[j10] += __shfl_xor_sync(0xffffffffu, pj[j10], m);
            int r = 2 * i + hh;          // 0..7
            if (og == r) {
                long brow = b0 + bg * 8 + r;
                #pragma unroll
                for (int j10 = 0; j10 < NOUTD; j10++)
                    out[brow * NOUTD + j10] = pj[j10] + b2s[j10];
            }
        }
    }
}

// =====================================================================
extern "C" void kernel_launch(void* const* d_in, const int* in_sizes, int n_in,
                              void* d_out, int out_size)
{
    const float* x     = (const float*)d_in[0];
    const float* w1    = (const float*)d_in[1];
    const float* b1    = (const float*)d_in[2];
    const float* coef  = (const float*)d_in[3];
    const float* wbias = (const float*)d_in[4];
    const float* w2    = (const float*)d_in[5];
    const float* b2    = (const float*)d_in[6];
    float* out = (float*)d_out;

    k_gemm1<<<BATCH / 128, 256>>>(x, w1, b1);
    k_kan<<<BATCH / 128, 128>>>(coef, wbias, w2, b2, out);
}